// round 1
// baseline (speedup 1.0000x reference)
#include <cuda_runtime.h>

#define N_USER   50000
#define N_ITEM   100000
#define N_NODES  150000
#define EMB      64
#define N_LAYERS 3
#define NNZ      2400000
#define BATCH    4096
#define ROWELEMS (N_NODES * EMB)   // 9,600,000 floats = 38.4 MB per buffer

// Persistent scratch (static __device__ arrays: no allocation at runtime).
// g_ego[0] = initial concat(user_emb, item_emb); g_ego[k+1] = leaky_relu output of layer k.
// g_norm[k] = row-normalized g_ego[k+1].
__device__ float g_ego[N_LAYERS + 1][ROWELEMS];
__device__ float g_norm[N_LAYERS][ROWELEMS];
__device__ float g_side[ROWELEMS];

// ---------------------------------------------------------------------------
// init: ego0 = concat(user_emb, item_emb)
// ---------------------------------------------------------------------------
__global__ void init_kernel(const float4* __restrict__ ue, const float4* __restrict__ ie) {
    int i = blockIdx.x * blockDim.x + threadIdx.x;
    const int NU4 = N_USER * EMB / 4;
    const int NT4 = ROWELEMS / 4;
    if (i >= NT4) return;
    float4 v = (i < NU4) ? ue[i] : ie[i - NU4];
    reinterpret_cast<float4*>(g_ego[0])[i] = v;
}

// ---------------------------------------------------------------------------
// zero the scatter target
// ---------------------------------------------------------------------------
__global__ void zero_kernel() {
    int i = blockIdx.x * blockDim.x + threadIdx.x;
    const int NT4 = ROWELEMS / 4;
    if (i >= NT4) return;
    reinterpret_cast<float4*>(g_side)[i] = make_float4(0.f, 0.f, 0.f, 0.f);
}

// ---------------------------------------------------------------------------
// SpMM: side[row] += val * ego[col]   (segment_sum of scaled gathered rows)
// 16 threads per edge, one float4 (16B) per thread, vectorized L2 reduction.
// ---------------------------------------------------------------------------
__global__ void spmm_kernel(const int* __restrict__ arow,
                            const int* __restrict__ acol,
                            const float* __restrict__ aval,
                            int ein) {
    int t = blockIdx.x * blockDim.x + threadIdx.x;   // up to NNZ*16 = 38.4M
    int e = t >> 4;
    if (e >= NNZ) return;
    int q = (t & 15) * 4;
    int r = arow[e];
    int c = acol[e];
    float v = aval[e];
    const float* ego = g_ego[ein];
    float4 x = *reinterpret_cast<const float4*>(ego + (size_t)c * EMB + q);
    float4 m = make_float4(x.x * v, x.y * v, x.z * v, x.w * v);
    float* p = g_side + (size_t)r * EMB + q;
    asm volatile("red.global.add.v4.f32 [%0], {%1, %2, %3, %4};"
                 :: "l"(p), "f"(m.x), "f"(m.y), "f"(m.z), "f"(m.w)
                 : "memory");
}

// ---------------------------------------------------------------------------
// Dense transform + leaky_relu + fused row-normalize.
//   out = leaky_relu(side @ Wgc + bgc + (ego*side) @ Wbi + bbi, 0.2)
//   norm_out = out / max(||out||_2, 1e-12)
// One thread owns one full row (64 outputs in registers). W tiles live in smem
// and are read with uniform-address (broadcast) LDS.128.
// ---------------------------------------------------------------------------
__global__ void __launch_bounds__(256) dense_kernel(
        const float* __restrict__ Wgc, const float* __restrict__ bgc,
        const float* __restrict__ Wbi, const float* __restrict__ bbi,
        int k) {
    __shared__ float4 sWg[EMB * EMB / 4];   // 4 KB * 4 = 16 KB
    __shared__ float4 sWb[EMB * EMB / 4];
    __shared__ float  sB[EMB];

    for (int i = threadIdx.x; i < EMB * EMB / 4; i += blockDim.x) {
        sWg[i] = reinterpret_cast<const float4*>(Wgc)[i];
        sWb[i] = reinterpret_cast<const float4*>(Wbi)[i];
    }
    for (int i = threadIdx.x; i < EMB; i += blockDim.x)
        sB[i] = bgc[i] + bbi[i];
    __syncthreads();

    const float* __restrict__ side = g_side;
    const float* __restrict__ ego  = g_ego[k];
    float* __restrict__ egonew     = g_ego[k + 1];
    float* __restrict__ normout    = g_norm[k];

    int stride = gridDim.x * blockDim.x;
    for (int row = blockIdx.x * blockDim.x + threadIdx.x; row < N_NODES; row += stride) {
        const float* sp = side + (size_t)row * EMB;
        const float* ep = ego  + (size_t)row * EMB;

        float acc[EMB];
        #pragma unroll
        for (int j = 0; j < EMB; j++) acc[j] = sB[j];

        for (int i = 0; i < EMB; i++) {
            float s = __ldg(sp + i);
            float u = __ldg(ep + i) * s;
            #pragma unroll
            for (int jc = 0; jc < EMB / 4; jc++) {
                float4 wg = sWg[i * (EMB / 4) + jc];
                float4 wb = sWb[i * (EMB / 4) + jc];
                acc[jc * 4 + 0] += s * wg.x + u * wb.x;
                acc[jc * 4 + 1] += s * wg.y + u * wb.y;
                acc[jc * 4 + 2] += s * wg.z + u * wb.z;
                acc[jc * 4 + 3] += s * wg.w + u * wb.w;
            }
        }

        // leaky_relu + L2 norm
        float ss = 0.f;
        #pragma unroll
        for (int j = 0; j < EMB; j++) {
            float v = acc[j];
            v = (v > 0.f) ? v : 0.2f * v;
            acc[j] = v;
            ss += v * v;
        }
        float inv = 1.0f / fmaxf(sqrtf(ss), 1e-12f);

        float4* eo = reinterpret_cast<float4*>(egonew  + (size_t)row * EMB);
        float4* no = reinterpret_cast<float4*>(normout + (size_t)row * EMB);
        #pragma unroll
        for (int jc = 0; jc < EMB / 4; jc++) {
            float4 v = make_float4(acc[jc*4+0], acc[jc*4+1], acc[jc*4+2], acc[jc*4+3]);
            eo[jc] = v;
            no[jc] = make_float4(v.x * inv, v.y * inv, v.z * inv, v.w * inv);
        }
    }
}

// ---------------------------------------------------------------------------
// Final gather: out rows = [ego_init | norm0 | norm1 | norm2] at selected nodes.
// Sections: [0,BATCH) users, [BATCH,2B) pos items, [2B,3B) neg items.
// One thread per float4 of output.
// ---------------------------------------------------------------------------
__global__ void gather_kernel(const int* __restrict__ users,
                              const int* __restrict__ pos,
                              const int* __restrict__ neg,
                              float* __restrict__ out) {
    int t = blockIdx.x * blockDim.x + threadIdx.x;   // < 3*BATCH*64
    if (t >= 3 * BATCH * (4 * EMB / 4)) return;
    int q = t & 63;          // float4 index within the 256-float output row
    int r = t >> 6;          // output row
    int s = r / BATCH;
    int b = r - s * BATCH;
    int node = (s == 0) ? users[b] : (N_USER + ((s == 1) ? pos[b] : neg[b]));
    int blk = q >> 4;        // which 64-col block (0 = init, 1..3 = norms)
    int qq  = q & 15;        // float4 within block
    const float* src = (blk == 0) ? g_ego[0] : g_norm[blk - 1];
    float4 v = *reinterpret_cast<const float4*>(src + (size_t)node * EMB + qq * 4);
    reinterpret_cast<float4*>(out)[(size_t)r * 64 + q] = v;
}

// ---------------------------------------------------------------------------
extern "C" void kernel_launch(void* const* d_in, const int* in_sizes, int n_in,
                              void* d_out, int out_size) {
    const int*   users    = (const int*)  d_in[0];
    const int*   pos      = (const int*)  d_in[1];
    const int*   neg      = (const int*)  d_in[2];
    const int*   arow     = (const int*)  d_in[3];
    const int*   acol     = (const int*)  d_in[4];
    const float* aval     = (const float*)d_in[5];
    const float* user_emb = (const float*)d_in[6];
    const float* item_emb = (const float*)d_in[7];
    const float* W_gc     = (const float*)d_in[8];
    const float* b_gc     = (const float*)d_in[9];
    const float* W_bi     = (const float*)d_in[10];
    const float* b_bi     = (const float*)d_in[11];
    float* out = (float*)d_out;

    const int VEC_BLOCKS  = (ROWELEMS / 4 + 255) / 256;   // 9375
    const int SPMM_BLOCKS = (NNZ * 16) / 256;             // 150000
    const int DENSE_BLOCKS = 592;
    const int GATHER_BLOCKS = (3 * BATCH * 64 + 255) / 256; // 3072

    init_kernel<<<VEC_BLOCKS, 256>>>((const float4*)user_emb, (const float4*)item_emb);

    for (int k = 0; k < N_LAYERS; k++) {
        zero_kernel<<<VEC_BLOCKS, 256>>>();
        spmm_kernel<<<SPMM_BLOCKS, 256>>>(arow, acol, aval, k);
        dense_kernel<<<DENSE_BLOCKS, 256>>>(W_gc + k * EMB * EMB, b_gc + k * EMB,
                                            W_bi + k * EMB * EMB, b_bi + k * EMB, k);
    }

    gather_kernel<<<GATHER_BLOCKS, 256>>>(users, pos, neg, out);
}

// round 2
// speedup vs baseline: 1.2803x; 1.2803x over previous
#include <cuda_runtime.h>

#define N_USER   50000
#define N_ITEM   100000
#define N_NODES  150000
#define EMB      64
#define N_LAYERS 3
#define NNZ      2400000
#define BATCH    4096
#define ROWELEMS (N_NODES * EMB)   // 9,600,000 floats = 38.4 MB per buffer

// Persistent scratch (static __device__ arrays: no runtime allocation).
__device__ float g_ego[N_LAYERS + 1][ROWELEMS];
__device__ float g_norm[N_LAYERS][ROWELEMS];
__device__ float g_side[ROWELEMS];

// packed f32x2 FMA: acc = a*b + acc (two independent fp32 lanes per issue slot)
#define FMA2(acc, a, b) \
    asm("fma.rn.f32x2 %0, %1, %2, %3;" : "=l"(acc) : "l"(a), "l"(b), "l"(acc))

__device__ __forceinline__ float f2lo(unsigned long long v) {
    return __uint_as_float((unsigned)(v & 0xffffffffull));
}
__device__ __forceinline__ float f2hi(unsigned long long v) {
    return __uint_as_float((unsigned)(v >> 32));
}

// ---------------------------------------------------------------------------
// init: ego0 = concat(user_emb, item_emb)
// ---------------------------------------------------------------------------
__global__ void init_kernel(const float4* __restrict__ ue, const float4* __restrict__ ie) {
    int i = blockIdx.x * blockDim.x + threadIdx.x;
    const int NU4 = N_USER * EMB / 4;
    const int NT4 = ROWELEMS / 4;
    if (i >= NT4) return;
    float4 v = (i < NU4) ? ue[i] : ie[i - NU4];
    reinterpret_cast<float4*>(g_ego[0])[i] = v;
}

__global__ void zero_kernel() {
    int i = blockIdx.x * blockDim.x + threadIdx.x;
    const int NT4 = ROWELEMS / 4;
    if (i >= NT4) return;
    reinterpret_cast<float4*>(g_side)[i] = make_float4(0.f, 0.f, 0.f, 0.f);
}

// ---------------------------------------------------------------------------
// SpMM: side[row] += val * ego[col].  16 threads/edge, red.global.add.v4.f32.
// ---------------------------------------------------------------------------
__global__ void spmm_kernel(const int* __restrict__ arow,
                            const int* __restrict__ acol,
                            const float* __restrict__ aval,
                            int ein) {
    int t = blockIdx.x * blockDim.x + threadIdx.x;
    int e = t >> 4;
    if (e >= NNZ) return;
    int q = (t & 15) * 4;
    int r = arow[e];
    int c = acol[e];
    float v = aval[e];
    const float* ego = g_ego[ein];
    float4 x = *reinterpret_cast<const float4*>(ego + (size_t)c * EMB + q);
    float4 m = make_float4(x.x * v, x.y * v, x.z * v, x.w * v);
    float* p = g_side + (size_t)r * EMB + q;
    asm volatile("red.global.add.v4.f32 [%0], {%1, %2, %3, %4};"
                 :: "l"(p), "f"(m.x), "f"(m.y), "f"(m.z), "f"(m.w)
                 : "memory");
}

// ---------------------------------------------------------------------------
// Dense: out = lrelu(h@Wg + (ego*h)@Wb + b), then row-normalize.
// Tiled GEMM: 64 rows x 64 cols per block, 256 threads, thread tile 4x4.
// f32x2 accumulators hold even/odd-k partial sums (zero packing overhead:
// h/p are k-contiguous in smem, W stored transposed so it is too).
// ---------------------------------------------------------------------------
__global__ void __launch_bounds__(256, 2) dense_kernel(
        const float4* __restrict__ Wgc, const float* __restrict__ bgc,
        const float4* __restrict__ Wbi, const float* __restrict__ bbi,
        int k) {
    extern __shared__ char smem[];
    // each region: 64*16 float4 = 16KB
    ulonglong2* sH  = reinterpret_cast<ulonglong2*>(smem);            // h[r][k4]
    ulonglong2* sP  = reinterpret_cast<ulonglong2*>(smem + 16384);    // p[r][k4]
    ulonglong2* sWg = reinterpret_cast<ulonglong2*>(smem + 32768);    // Wt[c][k4] swizzled
    ulonglong2* sWb = reinterpret_cast<ulonglong2*>(smem + 49152);
    float*      sB  = reinterpret_cast<float*>(smem + 65536);         // 64 floats

    const int tid = threadIdx.x;
    const int row0 = blockIdx.x * 64;

    const float4* side4 = reinterpret_cast<const float4*>(g_side);
    const float4* ego4  = reinterpret_cast<const float4*>(g_ego[k]);

    // stage h = side, p = ego*side (row-major, 16 float4 per row)
    for (int i = tid; i < 64 * 16; i += 256) {
        int r = i >> 4;
        int rr = row0 + r;
        if (rr >= N_NODES) rr = N_NODES - 1;          // clamp (stores guarded later)
        int gidx = rr * 16 + (i & 15);
        float4 s = side4[gidx];
        float4 e = ego4[gidx];
        reinterpret_cast<float4*>(sH)[i] = s;
        reinterpret_cast<float4*>(sP)[i] = make_float4(s.x*e.x, s.y*e.y, s.z*e.z, s.w*e.w);
    }
    // stage W transposed + XOR swizzle: element (kk, c) -> sW[c*16 + ((kk>>2) ^ (c&7))].f[kk&3]
    for (int i = tid; i < 64 * 16; i += 256) {
        int kk = i >> 4;            // k row of W
        int c4 = i & 15;
        float4 wg = Wgc[i];
        float4 wb = Wbi[i];
        const float* wgf = reinterpret_cast<const float*>(&wg);
        const float* wbf = reinterpret_cast<const float*>(&wb);
        int k4 = kk >> 2, ksub = kk & 3;
        #pragma unroll
        for (int j = 0; j < 4; j++) {
            int c = c4 * 4 + j;
            int idx = c * 16 + (k4 ^ (c & 7));
            reinterpret_cast<float*>(&sWg[idx])[ksub] = wgf[j];
            reinterpret_cast<float*>(&sWb[idx])[ksub] = wbf[j];
        }
    }
    if (tid < 64) sB[tid] = bgc[tid] + bbi[tid];
    __syncthreads();

    const int cg = tid & 15;        // column group: cols cidx*16 + cg
    const int rg = tid >> 4;        // row group: rows rg*4 + ridx

    unsigned long long acc[4][4];   // [ridx][cidx], f32x2 (even-k lane, odd-k lane)
    #pragma unroll
    for (int a = 0; a < 4; a++)
        #pragma unroll
        for (int b = 0; b < 4; b++) acc[a][b] = 0ull;

    int ccol[4], widx[4];
    #pragma unroll
    for (int cidx = 0; cidx < 4; cidx++) {
        ccol[cidx] = cidx * 16 + cg;
        widx[cidx] = ccol[cidx] * 16;
    }

    #pragma unroll 4
    for (int k4 = 0; k4 < 16; k4++) {
        ulonglong2 h2[4], p2[4];
        #pragma unroll
        for (int ridx = 0; ridx < 4; ridx++) {
            int r = rg * 4 + ridx;
            h2[ridx] = sH[r * 16 + k4];
            p2[ridx] = sP[r * 16 + k4];
        }
        ulonglong2 wg2[4], wb2[4];
        #pragma unroll
        for (int cidx = 0; cidx < 4; cidx++) {
            int idx = widx[cidx] + (k4 ^ (ccol[cidx] & 7));
            wg2[cidx] = sWg[idx];
            wb2[cidx] = sWb[idx];
        }
        #pragma unroll
        for (int ridx = 0; ridx < 4; ridx++) {
            #pragma unroll
            for (int cidx = 0; cidx < 4; cidx++) {
                FMA2(acc[ridx][cidx], h2[ridx].x, wg2[cidx].x);
                FMA2(acc[ridx][cidx], h2[ridx].y, wg2[cidx].y);
                FMA2(acc[ridx][cidx], p2[ridx].x, wb2[cidx].x);
                FMA2(acc[ridx][cidx], p2[ridx].y, wb2[cidx].y);
            }
        }
    }

    // epilogue: combine lanes, bias, leaky_relu, row-norm via half-warp shuffle
    float out[4][4];
    float ssr[4];
    #pragma unroll
    for (int ridx = 0; ridx < 4; ridx++) {
        ssr[ridx] = 0.f;
        #pragma unroll
        for (int cidx = 0; cidx < 4; cidx++) {
            float v = f2lo(acc[ridx][cidx]) + f2hi(acc[ridx][cidx]) + sB[ccol[cidx]];
            v = (v > 0.f) ? v : 0.2f * v;
            out[ridx][cidx] = v;
            ssr[ridx] += v * v;
        }
    }
    #pragma unroll
    for (int ridx = 0; ridx < 4; ridx++) {
        float s = ssr[ridx];
        #pragma unroll
        for (int m = 1; m < 16; m <<= 1)
            s += __shfl_xor_sync(0xffffffffu, s, m, 16);
        ssr[ridx] = 1.0f / fmaxf(sqrtf(s), 1e-12f);
    }

    float* __restrict__ egonew  = g_ego[k + 1];
    float* __restrict__ normout = g_norm[k];
    #pragma unroll
    for (int ridx = 0; ridx < 4; ridx++) {
        int row = row0 + rg * 4 + ridx;
        if (row < N_NODES) {
            #pragma unroll
            for (int cidx = 0; cidx < 4; cidx++) {
                float v = out[ridx][cidx];
                egonew [(size_t)row * EMB + ccol[cidx]] = v;
                normout[(size_t)row * EMB + ccol[cidx]] = v * ssr[ridx];
            }
        }
    }
}

// ---------------------------------------------------------------------------
// Final gather: out rows = [ego_init | norm0 | norm1 | norm2] at selected nodes.
// ---------------------------------------------------------------------------
__global__ void gather_kernel(const int* __restrict__ users,
                              const int* __restrict__ pos,
                              const int* __restrict__ neg,
                              float* __restrict__ out) {
    int t = blockIdx.x * blockDim.x + threadIdx.x;
    if (t >= 3 * BATCH * 64) return;
    int q = t & 63;          // float4 index within the 256-float output row
    int r = t >> 6;          // output row
    int s = r / BATCH;
    int b = r - s * BATCH;
    int node = (s == 0) ? users[b] : (N_USER + ((s == 1) ? pos[b] : neg[b]));
    int blk = q >> 4;
    int qq  = q & 15;
    const float* src = (blk == 0) ? g_ego[0] : g_norm[blk - 1];
    float4 v = *reinterpret_cast<const float4*>(src + (size_t)node * EMB + qq * 4);
    reinterpret_cast<float4*>(out)[(size_t)r * 64 + q] = v;
}

// ---------------------------------------------------------------------------
extern "C" void kernel_launch(void* const* d_in, const int* in_sizes, int n_in,
                              void* d_out, int out_size) {
    const int*   users    = (const int*)  d_in[0];
    const int*   pos      = (const int*)  d_in[1];
    const int*   neg      = (const int*)  d_in[2];
    const int*   arow     = (const int*)  d_in[3];
    const int*   acol     = (const int*)  d_in[4];
    const float* aval     = (const float*)d_in[5];
    const float* user_emb = (const float*)d_in[6];
    const float* item_emb = (const float*)d_in[7];
    const float* W_gc     = (const float*)d_in[8];
    const float* b_gc     = (const float*)d_in[9];
    const float* W_bi     = (const float*)d_in[10];
    const float* b_bi     = (const float*)d_in[11];
    float* out = (float*)d_out;

    const int DSMEM = 65536 + 256;   // h+p+Wg+Wb + bias
    static int attr_done = 0;
    if (!attr_done) {
        cudaFuncSetAttribute(dense_kernel, cudaFuncAttributeMaxDynamicSharedMemorySize, DSMEM);
        attr_done = 1;
    }

    const int VEC_BLOCKS    = (ROWELEMS / 4 + 255) / 256;     // 9375
    const int SPMM_BLOCKS   = (NNZ * 16) / 256;               // 150000
    const int DENSE_BLOCKS  = (N_NODES + 63) / 64;            // 2344
    const int GATHER_BLOCKS = (3 * BATCH * 64 + 255) / 256;   // 3072

    init_kernel<<<VEC_BLOCKS, 256>>>((const float4*)user_emb, (const float4*)item_emb);

    for (int k = 0; k < N_LAYERS; k++) {
        zero_kernel<<<VEC_BLOCKS, 256>>>();
        spmm_kernel<<<SPMM_BLOCKS, 256>>>(arow, acol, aval, k);
        dense_kernel<<<DENSE_BLOCKS, 256, DSMEM>>>(
            (const float4*)(W_gc + k * EMB * EMB), b_gc + k * EMB,
            (const float4*)(W_bi + k * EMB * EMB), b_bi + k * EMB, k);
    }

    gather_kernel<<<GATHER_BLOCKS, 256>>>(users, pos, neg, out);
}

// round 3
// speedup vs baseline: 1.8562x; 1.4498x over previous
#include <cuda_runtime.h>

#define N_USER   50000
#define N_ITEM   100000
#define N_NODES  150000
#define EMB      64
#define N_LAYERS 3
#define NNZ      2400000
#define BATCH    4096
#define ROWELEMS (N_NODES * EMB)     // 9,600,000 floats = 38.4 MB per buffer
#define SCAN_BLOCKS 586              // ceil(N_NODES / 256)

// Persistent scratch (static __device__ arrays: no runtime allocation).
__device__ float g_ego[N_LAYERS + 1][ROWELEMS];
__device__ float g_norm[N_LAYERS][ROWELEMS];
__device__ float g_side[ROWELEMS];

// CSR build scratch
__device__ int  g_cnt[N_NODES];
__device__ int  g_off[N_NODES + 1];
__device__ int  g_cur[N_NODES];
__device__ int  g_bsum[SCAN_BLOCKS];
__device__ int  g_bpre[SCAN_BLOCKS];
__device__ int2 g_edge[NNZ];         // (col, float-bits of val), grouped by row

// packed f32x2 FMA: acc = a*b + acc
#define FMA2(acc, a, b) \
    asm("fma.rn.f32x2 %0, %1, %2, %3;" : "=l"(acc) : "l"(a), "l"(b), "l"(acc))

__device__ __forceinline__ float f2lo(unsigned long long v) {
    return __uint_as_float((unsigned)(v & 0xffffffffull));
}
__device__ __forceinline__ float f2hi(unsigned long long v) {
    return __uint_as_float((unsigned)(v >> 32));
}

// ---------------------------------------------------------------------------
// init: ego0 = concat(user_emb, item_emb)
// ---------------------------------------------------------------------------
__global__ void init_kernel(const float4* __restrict__ ue, const float4* __restrict__ ie) {
    int i = blockIdx.x * blockDim.x + threadIdx.x;
    const int NU4 = N_USER * EMB / 4;
    const int NT4 = ROWELEMS / 4;
    if (i >= NT4) return;
    float4 v = (i < NU4) ? ue[i] : ie[i - NU4];
    reinterpret_cast<float4*>(g_ego[0])[i] = v;
}

// ---------------------------------------------------------------------------
// CSR build: zero counts -> histogram -> 2-level exclusive scan -> scatter
// ---------------------------------------------------------------------------
__global__ void zero_cnt_kernel() {
    int i = blockIdx.x * blockDim.x + threadIdx.x;
    if (i < N_NODES) g_cnt[i] = 0;
}

__global__ void hist_kernel(const int* __restrict__ arow) {
    int e = blockIdx.x * blockDim.x + threadIdx.x;
    if (e >= NNZ) return;
    atomicAdd(&g_cnt[arow[e]], 1);
}

__global__ void scan1_kernel() {            // per-block sums of 256 counts
    __shared__ int s[256];
    int t = threadIdx.x;
    int i = blockIdx.x * 256 + t;
    s[t] = (i < N_NODES) ? g_cnt[i] : 0;
    __syncthreads();
    for (int d = 128; d > 0; d >>= 1) {
        if (t < d) s[t] += s[t + d];
        __syncthreads();
    }
    if (t == 0) g_bsum[blockIdx.x] = s[0];
}

__global__ void scan2_kernel() {            // single-block exclusive scan of block sums
    __shared__ int s[1024];
    int t = threadIdx.x;
    int v = (t < SCAN_BLOCKS) ? g_bsum[t] : 0;
    s[t] = v;
    __syncthreads();
    for (int d = 1; d < 1024; d <<= 1) {
        int add = (t >= d) ? s[t - d] : 0;
        __syncthreads();
        s[t] += add;
        __syncthreads();
    }
    if (t < SCAN_BLOCKS) g_bpre[t] = s[t] - v;   // exclusive
    if (t == 0) g_off[N_NODES] = NNZ;
}

__global__ void scan3_kernel() {            // final offsets
    __shared__ int s[256];
    int t = threadIdx.x;
    int i = blockIdx.x * 256 + t;
    int v = (i < N_NODES) ? g_cnt[i] : 0;
    s[t] = v;
    __syncthreads();
    for (int d = 1; d < 256; d <<= 1) {
        int add = (t >= d) ? s[t - d] : 0;
        __syncthreads();
        s[t] += add;
        __syncthreads();
    }
    if (i < N_NODES) {
        int off = g_bpre[blockIdx.x] + s[t] - v;
        g_off[i] = off;
        g_cur[i] = off;
    }
}

__global__ void scatter_kernel(const int* __restrict__ arow,
                               const int* __restrict__ acol,
                               const float* __restrict__ aval) {
    int e = blockIdx.x * blockDim.x + threadIdx.x;
    if (e >= NNZ) return;
    int r = arow[e];
    int pos = atomicAdd(&g_cur[r], 1);
    g_edge[pos] = make_int2(acol[e], __float_as_int(aval[e]));
}

// ---------------------------------------------------------------------------
// SpMM over CSR: warp per row. Lane owns 2 columns (float2). Messages are
// accumulated in registers; one 256B coalesced store per row. No RED traffic.
// ---------------------------------------------------------------------------
__global__ void spmm_sorted_kernel(int ein) {
    int gtid = blockIdx.x * blockDim.x + threadIdx.x;
    int row  = gtid >> 5;
    if (row >= N_NODES) return;
    int lane = threadIdx.x & 31;

    int beg = g_off[row];
    int end = g_off[row + 1];
    const float* __restrict__ ego = g_ego[ein];

    float2 acc = make_float2(0.f, 0.f);
    for (int e = beg; e < end; e++) {
        int2 cv = g_edge[e];                              // broadcast load
        float v = __int_as_float(cv.y);
        float2 x = reinterpret_cast<const float2*>(ego + (size_t)cv.x * EMB)[lane];
        acc.x += v * x.x;
        acc.y += v * x.y;
    }
    reinterpret_cast<float2*>(g_side + (size_t)row * EMB)[lane] = acc;
}

// ---------------------------------------------------------------------------
// Dense: out = lrelu(h@Wg + (ego*h)@Wb + b), then row-normalize.
// 64x64 block tile, 256 threads, 4x4 thread tile, f32x2 accumulators.
// sH/sP padded to stride 17 (16B units) to kill the 2-way bank conflict.
// ---------------------------------------------------------------------------
#define HP_STRIDE 17
__global__ void __launch_bounds__(256, 2) dense_kernel(
        const float4* __restrict__ Wgc, const float* __restrict__ bgc,
        const float4* __restrict__ Wbi, const float* __restrict__ bbi,
        int k) {
    extern __shared__ char smem[];
    ulonglong2* sH  = reinterpret_cast<ulonglong2*>(smem);                 // 64*17*16 = 17408
    ulonglong2* sP  = reinterpret_cast<ulonglong2*>(smem + 17408);         // 17408
    ulonglong2* sWg = reinterpret_cast<ulonglong2*>(smem + 34816);         // 16384
    ulonglong2* sWb = reinterpret_cast<ulonglong2*>(smem + 51200);         // 16384
    float*      sB  = reinterpret_cast<float*>(smem + 67584);              // 256

    const int tid = threadIdx.x;
    const int row0 = blockIdx.x * 64;

    const float4* side4 = reinterpret_cast<const float4*>(g_side);
    const float4* ego4  = reinterpret_cast<const float4*>(g_ego[k]);

    // stage h = side, p = ego*side
    for (int i = tid; i < 64 * 16; i += 256) {
        int r = i >> 4, c = i & 15;
        int rr = row0 + r;
        if (rr >= N_NODES) rr = N_NODES - 1;
        int gidx = rr * 16 + c;
        float4 s = side4[gidx];
        float4 e = ego4[gidx];
        *reinterpret_cast<float4*>(&sH[r * HP_STRIDE + c]) = s;
        *reinterpret_cast<float4*>(&sP[r * HP_STRIDE + c]) =
            make_float4(s.x * e.x, s.y * e.y, s.z * e.z, s.w * e.w);
    }
    // stage W transposed + XOR swizzle: (kk, c) -> sW[c*16 + ((kk>>2) ^ (c&7))].f[kk&3]
    for (int i = tid; i < 64 * 16; i += 256) {
        int kk = i >> 4;
        int c4 = i & 15;
        float4 wg = Wgc[i];
        float4 wb = Wbi[i];
        const float* wgf = reinterpret_cast<const float*>(&wg);
        const float* wbf = reinterpret_cast<const float*>(&wb);
        int k4 = kk >> 2, ksub = kk & 3;
        #pragma unroll
        for (int j = 0; j < 4; j++) {
            int c = c4 * 4 + j;
            int idx = c * 16 + (k4 ^ (c & 7));
            reinterpret_cast<float*>(&sWg[idx])[ksub] = wgf[j];
            reinterpret_cast<float*>(&sWb[idx])[ksub] = wbf[j];
        }
    }
    if (tid < 64) sB[tid] = bgc[tid] + bbi[tid];
    __syncthreads();

    const int cg = tid & 15;
    const int rg = tid >> 4;

    unsigned long long acc[4][4];
    #pragma unroll
    for (int a = 0; a < 4; a++)
        #pragma unroll
        for (int b = 0; b < 4; b++) acc[a][b] = 0ull;

    int ccol[4], widx[4];
    #pragma unroll
    for (int cidx = 0; cidx < 4; cidx++) {
        ccol[cidx] = cidx * 16 + cg;
        widx[cidx] = ccol[cidx] * 16;
    }

    #pragma unroll 4
    for (int k4 = 0; k4 < 16; k4++) {
        ulonglong2 h2[4], p2[4];
        #pragma unroll
        for (int ridx = 0; ridx < 4; ridx++) {
            int r = rg * 4 + ridx;
            h2[ridx] = sH[r * HP_STRIDE + k4];
            p2[ridx] = sP[r * HP_STRIDE + k4];
        }
        ulonglong2 wg2[4], wb2[4];
        #pragma unroll
        for (int cidx = 0; cidx < 4; cidx++) {
            int idx = widx[cidx] + (k4 ^ (ccol[cidx] & 7));
            wg2[cidx] = sWg[idx];
            wb2[cidx] = sWb[idx];
        }
        #pragma unroll
        for (int ridx = 0; ridx < 4; ridx++) {
            #pragma unroll
            for (int cidx = 0; cidx < 4; cidx++) {
                FMA2(acc[ridx][cidx], h2[ridx].x, wg2[cidx].x);
                FMA2(acc[ridx][cidx], h2[ridx].y, wg2[cidx].y);
                FMA2(acc[ridx][cidx], p2[ridx].x, wb2[cidx].x);
                FMA2(acc[ridx][cidx], p2[ridx].y, wb2[cidx].y);
            }
        }
    }

    // epilogue: combine lanes, bias, leaky_relu, row-norm via half-warp shuffle
    float out[4][4];
    float ssr[4];
    #pragma unroll
    for (int ridx = 0; ridx < 4; ridx++) {
        ssr[ridx] = 0.f;
        #pragma unroll
        for (int cidx = 0; cidx < 4; cidx++) {
            float v = f2lo(acc[ridx][cidx]) + f2hi(acc[ridx][cidx]) + sB[ccol[cidx]];
            v = (v > 0.f) ? v : 0.2f * v;
            out[ridx][cidx] = v;
            ssr[ridx] += v * v;
        }
    }
    #pragma unroll
    for (int ridx = 0; ridx < 4; ridx++) {
        float s = ssr[ridx];
        #pragma unroll
        for (int m = 1; m < 16; m <<= 1)
            s += __shfl_xor_sync(0xffffffffu, s, m, 16);
        ssr[ridx] = 1.0f / fmaxf(sqrtf(s), 1e-12f);
    }

    float* __restrict__ egonew  = g_ego[k + 1];
    float* __restrict__ normout = g_norm[k];
    #pragma unroll
    for (int ridx = 0; ridx < 4; ridx++) {
        int row = row0 + rg * 4 + ridx;
        if (row < N_NODES) {
            #pragma unroll
            for (int cidx = 0; cidx < 4; cidx++) {
                float v = out[ridx][cidx];
                egonew [(size_t)row * EMB + ccol[cidx]] = v;
                normout[(size_t)row * EMB + ccol[cidx]] = v * ssr[ridx];
            }
        }
    }
}

// ---------------------------------------------------------------------------
// Final gather: out rows = [ego_init | norm0 | norm1 | norm2] at selected nodes.
// ---------------------------------------------------------------------------
__global__ void gather_kernel(const int* __restrict__ users,
                              const int* __restrict__ pos,
                              const int* __restrict__ neg,
                              float* __restrict__ out) {
    int t = blockIdx.x * blockDim.x + threadIdx.x;
    if (t >= 3 * BATCH * 64) return;
    int q = t & 63;
    int r = t >> 6;
    int s = r / BATCH;
    int b = r - s * BATCH;
    int node = (s == 0) ? users[b] : (N_USER + ((s == 1) ? pos[b] : neg[b]));
    int blk = q >> 4;
    int qq  = q & 15;
    const float* src = (blk == 0) ? g_ego[0] : g_norm[blk - 1];
    float4 v = *reinterpret_cast<const float4*>(src + (size_t)node * EMB + qq * 4);
    reinterpret_cast<float4*>(out)[(size_t)r * 64 + q] = v;
}

// ---------------------------------------------------------------------------
extern "C" void kernel_launch(void* const* d_in, const int* in_sizes, int n_in,
                              void* d_out, int out_size) {
    const int*   users    = (const int*)  d_in[0];
    const int*   pos      = (const int*)  d_in[1];
    const int*   neg      = (const int*)  d_in[2];
    const int*   arow     = (const int*)  d_in[3];
    const int*   acol     = (const int*)  d_in[4];
    const float* aval     = (const float*)d_in[5];
    const float* user_emb = (const float*)d_in[6];
    const float* item_emb = (const float*)d_in[7];
    const float* W_gc     = (const float*)d_in[8];
    const float* b_gc     = (const float*)d_in[9];
    const float* W_bi     = (const float*)d_in[10];
    const float* b_bi     = (const float*)d_in[11];
    float* out = (float*)d_out;

    const int DSMEM = 67584 + 256;
    static int attr_done = 0;
    if (!attr_done) {
        cudaFuncSetAttribute(dense_kernel, cudaFuncAttributeMaxDynamicSharedMemorySize, DSMEM);
        attr_done = 1;
    }

    const int VEC_BLOCKS    = (ROWELEMS / 4 + 255) / 256;       // 9375
    const int EDGE_BLOCKS   = (NNZ + 255) / 256;                // 9375
    const int NODE_BLOCKS   = (N_NODES + 255) / 256;            // 586
    const int SPMM_BLOCKS   = (N_NODES * 32 + 255) / 256;       // 18750
    const int DENSE_BLOCKS  = (N_NODES + 63) / 64;              // 2344
    const int GATHER_BLOCKS = (3 * BATCH * 64 + 255) / 256;     // 3072

    init_kernel<<<VEC_BLOCKS, 256>>>((const float4*)user_emb, (const float4*)item_emb);

    // CSR build (once; reused by all 3 layers)
    zero_cnt_kernel<<<NODE_BLOCKS, 256>>>();
    hist_kernel<<<EDGE_BLOCKS, 256>>>(arow);
    scan1_kernel<<<SCAN_BLOCKS, 256>>>();
    scan2_kernel<<<1, 1024>>>();
    scan3_kernel<<<SCAN_BLOCKS, 256>>>();
    scatter_kernel<<<EDGE_BLOCKS, 256>>>(arow, acol, aval);

    for (int k = 0; k < N_LAYERS; k++) {
        spmm_sorted_kernel<<<SPMM_BLOCKS, 256>>>(k);
        dense_kernel<<<DENSE_BLOCKS, 256, DSMEM>>>(
            (const float4*)(W_gc + k * EMB * EMB), b_gc + k * EMB,
            (const float4*)(W_bi + k * EMB * EMB), b_bi + k * EMB, k);
    }

    gather_kernel<<<GATHER_BLOCKS, 256>>>(users, pos, neg, out);
}